// round 5
// baseline (speedup 1.0000x reference)
#include <cuda_runtime.h>
#include <cuda_bf16.h>
#include <cuda_fp8.h>
#include <stdint.h>
#include <math.h>

#define NROWS 8192
#define HALF_N 4096
#define DDIM 256

// Scratch (allocation-free rule: __device__ globals)
__device__ uint8_t g_reps[NROWS * DDIM];         // e4m3, normalized * sqrt(2*log2 e)
__device__ float g_spart[2][2][NROWS];           // [col-half][group] partial sums
__device__ float g_pos[NROWS];                   // positive logit (natural log domain)
__device__ float g_rpart[32];
__device__ int g_sem;                            // zero-init; reset each launch

static __device__ __forceinline__ float ex2f(float x) {
    float y;
    asm("ex2.approx.f32 %0, %1;" : "=f"(y) : "f"(x));
    return y;
}

static __device__ __forceinline__ void ldsm4(uint32_t& r0, uint32_t& r1,
                                             uint32_t& r2, uint32_t& r3, uint32_t addr) {
    asm volatile("ldmatrix.sync.aligned.m8n8.x4.shared.b16 {%0,%1,%2,%3}, [%4];"
                 : "=r"(r0), "=r"(r1), "=r"(r2), "=r"(r3) : "r"(addr));
}

static __device__ __forceinline__ void mma_fp8(float c[4], const uint32_t a[4],
                                               const uint32_t b[2]) {
    asm volatile(
        "mma.sync.aligned.m16n8k32.row.col.f32.e4m3.e4m3.f32 "
        "{%0,%1,%2,%3}, {%4,%5,%6,%7}, {%8,%9}, {%0,%1,%2,%3};"
        : "+f"(c[0]), "+f"(c[1]), "+f"(c[2]), "+f"(c[3])
        : "r"(a[0]), "r"(a[1]), "r"(a[2]), "r"(a[3]), "r"(b[0]), "r"(b[1]));
}

static __device__ __forceinline__ void cpasync16(uint32_t dst, const void* src) {
    asm volatile("cp.async.cg.shared.global [%0], [%1], 16;" :: "r"(dst), "l"(src));
}
#define CP_COMMIT() asm volatile("cp.async.commit_group;")
#define CP_WAIT1()  asm volatile("cp.async.wait_group 1;")
#define CP_WAIT0()  asm volatile("cp.async.wait_group 0;")
#define BAR_G(id)   asm volatile("bar.sync %0, 128;" :: "r"(id) : "memory")

static __device__ __forceinline__ uint16_t cvt_e4m3x2(float hi, float lo) {
    uint16_t r;
    asm("cvt.rn.satfinite.e4m3x2.f32 %0, %1, %2;" : "=h"(r) : "f"(hi), "f"(lo));
    return r;
}

// Swizzled 16B-chunk offset within a 256B row: chunks 0..15, XOR low 3 bits.
static __device__ __forceinline__ uint32_t swz(int chunk, int r) {
    return (uint32_t)(((chunk & 8) | ((chunk & 7) ^ (r & 7))) << 4);
}

// ---------------------------------------------------------------------------
// Kernel 1: L2-normalize rows of [emb_i; emb_j]; write e4m3 scaled by
// sqrt(2*log2 e) (product of two rows then carries 2*log2(e) -> base-2 logits).
// ---------------------------------------------------------------------------
__global__ void k_norm(const float* __restrict__ ei, const float* __restrict__ ej) {
    const float SQ = 1.69864362f;  // sqrt(2 * log2(e))
    int warp = threadIdx.x >> 5;
    int lane = threadIdx.x & 31;
    int row0 = blockIdx.x * 16 + warp * 2;

#pragma unroll
    for (int rr = 0; rr < 2; rr++) {
        int row = row0 + rr;
        const float* src = (row < HALF_N) ? (ei + (size_t)row * DDIM)
                                          : (ej + (size_t)(row - HALF_N) * DDIM);
        float4 v0 = ((const float4*)src)[lane * 2];
        float4 v1 = ((const float4*)src)[lane * 2 + 1];
        float ss = v0.x * v0.x + v0.y * v0.y + v0.z * v0.z + v0.w * v0.w
                 + v1.x * v1.x + v1.y * v1.y + v1.z * v1.z + v1.w * v1.w;
#pragma unroll
        for (int o = 16; o > 0; o >>= 1) ss += __shfl_xor_sync(0xFFFFFFFFu, ss, o);
        float sa = SQ / fmaxf(sqrtf(ss), 1e-12f);

        uint32_t p0 = (uint32_t)cvt_e4m3x2(v0.y * sa, v0.x * sa)
                    | ((uint32_t)cvt_e4m3x2(v0.w * sa, v0.z * sa) << 16);
        uint32_t p1 = (uint32_t)cvt_e4m3x2(v1.y * sa, v1.x * sa)
                    | ((uint32_t)cvt_e4m3x2(v1.w * sa, v1.z * sa) << 16);
        uint2* dst = (uint2*)(g_reps + (size_t)row * DDIM + lane * 8);
        *dst = make_uint2(p0, p1);
    }
}

// ---------------------------------------------------------------------------
// Kernel 2: fused FP8 GEMM + exp + row-sum.
// grid (2, 64): x = column half (4096 cols), y = row block of 128.
// 256 threads = 2 groups of 4 warps; group g handles 64-col tiles t=g,g+2,...
// A fragments (fp8, K=256) live in REGISTERS for the whole kernel; only B
// streams through smem (cp.async double buffer per group, named barriers).
// smem: A staging 32KB (used once) + 4 x B 64x256B (16KB each).
// ---------------------------------------------------------------------------
__global__ void __launch_bounds__(256) k_main() {
    extern __shared__ unsigned char smem[];
    const float LN2 = 0.6931471805599453f;

    int tid = threadIdx.x;
    int lane = tid & 31;
    int warp = tid >> 5;
    int wm = warp & 3;        // 32-row group within 128
    int g = warp >> 2;        // phase group
    int tidg = tid & 127;
    int cb = blockIdx.x;
    int rb = blockIdx.y;
    int row0 = rb * 128;

    uint32_t sb = (uint32_t)__cvta_generic_to_shared(smem);
    uint32_t Abase = sb;
    uint32_t Bbuf[2];
    Bbuf[0] = sb + 32768 + (g * 2 + 0) * 16384;
    Bbuf[1] = sb + 32768 + (g * 2 + 1) * 16384;

    const uint4* reps16 = (const uint4*)g_reps;  // 16B chunks

    // ---- Stage A tile (128 rows x 256B) + first B tile of this group.
    {
        // A: 2048 chunks, all 256 threads.
#pragma unroll
        for (int it = 0; it < 8; it++) {
            int idx = it * 256 + tid;
            int r = idx >> 4, c = idx & 15;
            cpasync16(Abase + r * 256 + swz(c, r), reps16 + (size_t)row0 * 16 + idx);
        }
        // B tile t=g: 1024 chunks, this group's 128 threads.
        const uint4* srcB = reps16 + (size_t)(cb * 4096 + g * 64) * 16;
#pragma unroll
        for (int it = 0; it < 8; it++) {
            int idx = it * 128 + tidg;
            int r = idx >> 4, c = idx & 15;
            cpasync16(Bbuf[0] + r * 256 + swz(c, r), srcB + idx);
        }
        CP_COMMIT();
        // B tile t=g+2:
        const uint4* srcB1 = reps16 + (size_t)(cb * 4096 + (g + 2) * 64) * 16;
#pragma unroll
        for (int it = 0; it < 8; it++) {
            int idx = it * 128 + tidg;
            int r = idx >> 4, c = idx & 15;
            cpasync16(Bbuf[1] + r * 256 + swz(c, r), srcB1 + idx);
        }
        CP_COMMIT();
    }
    CP_WAIT1();           // A + B[0] complete
    __syncthreads();

    // ---- Load A fragments into registers (held for all 32 tiles).
    uint32_t afr[2][8][4];
    {
        int aRow0 = wm * 32 + (lane & 15);
        int aCo = lane >> 4;
#pragma unroll
        for (int mt = 0; mt < 2; mt++) {
#pragma unroll
            for (int ks = 0; ks < 8; ks++) {
                int r = aRow0 + mt * 16;
                uint32_t addr = Abase + r * 256 + swz(ks * 2 + aCo, r);
                ldsm4(afr[mt][ks][0], afr[mt][ks][1], afr[mt][ks][2], afr[mt][ks][3], addr);
            }
        }
    }

    int bRowBase = (lane & 7) + ((lane & 16) >> 1);
    int bCo = (lane >> 3) & 1;
    int myRow0 = row0 + wm * 32;
    int pcol0 = (myRow0 + 4096) & 8191;
    float s[4] = {0.f, 0.f, 0.f, 0.f};

#pragma unroll 1
    for (int i = 0; i < 32; i++) {
        int t = g + 2 * i;
        int c0w = cb * 4096 + t * 64;
        uint32_t Bs = Bbuf[i & 1];

        float acc[2][8][4];
#pragma unroll
        for (int mt = 0; mt < 2; mt++)
#pragma unroll
            for (int nt = 0; nt < 8; nt++)
#pragma unroll
                for (int e = 0; e < 4; e++) acc[mt][nt][e] = 0.f;

#pragma unroll
        for (int ks = 0; ks < 8; ks++) {
            uint32_t b[8][2];
#pragma unroll
            for (int nb = 0; nb < 4; nb++) {
                int r = bRowBase + nb * 16;
                uint32_t addr = Bs + r * 256 + swz(ks * 2 + bCo, r);
                uint32_t r0, r1, r2, r3;
                ldsm4(r0, r1, r2, r3, addr);
                b[nb * 2][0] = r0;     b[nb * 2][1] = r1;
                b[nb * 2 + 1][0] = r2; b[nb * 2 + 1][1] = r3;
            }
#pragma unroll
            for (int mt = 0; mt < 2; mt++)
#pragma unroll
                for (int nt = 0; nt < 8; nt++) mma_fp8(acc[mt][nt], afr[mt][ks], b[nt]);
        }

        // Epilogue: exp2 + row sums; diag mask + positive capture.
        bool hasdiag = ((unsigned)(myRow0 - c0w) < 64u);
        bool haspos = ((unsigned)(pcol0 - c0w) < 64u);
        bool special = hasdiag || haspos;

#pragma unroll
        for (int mt = 0; mt < 2; mt++) {
            int rA = myRow0 + mt * 16 + (lane >> 2);
            int rB = rA + 8;
#pragma unroll
            for (int nt = 0; nt < 8; nt++) {
                float vx = acc[mt][nt][0], vy = acc[mt][nt][1];
                float vz = acc[mt][nt][2], vw = acc[mt][nt][3];
                int c = c0w + nt * 8 + (lane & 3) * 2;
                float e0 = ex2f(vx), e1 = ex2f(vy), e2 = ex2f(vz), e3 = ex2f(vw);
                if (special) {
                    if (c == rA) e0 = 0.f;
                    if (c + 1 == rA) e1 = 0.f;
                    if (c == rB) e2 = 0.f;
                    if (c + 1 == rB) e3 = 0.f;
                    int pA = (rA + 4096) & 8191;
                    int pB = (rB + 4096) & 8191;
                    if (c == pA) g_pos[rA] = vx * LN2;
                    if (c + 1 == pA) g_pos[rA] = vy * LN2;
                    if (c == pB) g_pos[rB] = vz * LN2;
                    if (c + 1 == pB) g_pos[rB] = vw * LN2;
                }
                s[mt * 2 + 0] += e0 + e1;
                s[mt * 2 + 1] += e2 + e3;
            }
        }

        // Refill the just-consumed buffer with tile t+4.
        BAR_G(g + 1);
        if (i < 30) {
            const uint4* src = reps16 + (size_t)(c0w + 256) * 16;
#pragma unroll
            for (int it = 0; it < 8; it++) {
                int idx = it * 128 + tidg;
                int r = idx >> 4, c = idx & 15;
                cpasync16(Bbuf[i & 1] + r * 256 + swz(c, r), src + idx);
            }
            CP_COMMIT();
            CP_WAIT1();
        } else {
            CP_WAIT0();
        }
        BAR_G(g + 1);
    }

    // Quad-reduce per row, store per (col-half, group).
#pragma unroll
    for (int i = 0; i < 4; i++) {
        s[i] += __shfl_xor_sync(0xFFFFFFFFu, s[i], 1);
        s[i] += __shfl_xor_sync(0xFFFFFFFFu, s[i], 2);
    }
    if ((lane & 3) == 0) {
        int r = myRow0 + (lane >> 2);
        g_spart[cb][g][r]      = s[0];
        g_spart[cb][g][r + 8]  = s[1];
        g_spart[cb][g][r + 16] = s[2];
        g_spart[cb][g][r + 24] = s[3];
    }
}

// ---------------------------------------------------------------------------
// Kernel 3: final reduction -> scalar loss (deterministic fixed-order finish).
// ---------------------------------------------------------------------------
__global__ void k_reduce(float* __restrict__ out) {
    __shared__ float red[256];
    __shared__ int isLast;
    int tid = threadIdx.x;
    int r = blockIdx.x * 256 + tid;
    float sden = g_spart[0][0][r] + g_spart[0][1][r]
               + g_spart[1][0][r] + g_spart[1][1][r];
    red[tid] = logf(sden) - g_pos[r];
    __syncthreads();
#pragma unroll
    for (int o = 128; o > 0; o >>= 1) {
        if (tid < o) red[tid] += red[tid + o];
        __syncthreads();
    }
    if (tid == 0) {
        g_rpart[blockIdx.x] = red[0];
        __threadfence();
        int old = atomicAdd(&g_sem, 1);
        isLast = (old == 31);
    }
    __syncthreads();
    if (tid == 0 && isLast) {
        __threadfence();
        volatile float* rp = g_rpart;
        float a = 0.f;
        for (int i = 0; i < 32; i++) a += rp[i];
        out[0] = a * (1.0f / 8192.0f);
        g_sem = 0;
    }
}

extern "C" void kernel_launch(void* const* d_in, const int* in_sizes, int n_in,
                              void* d_out, int out_size) {
    const float* ei = (const float*)d_in[0];
    const float* ej = (const float*)d_in[1];
    (void)in_sizes; (void)n_in; (void)out_size;

    cudaFuncSetAttribute(k_main, cudaFuncAttributeMaxDynamicSharedMemorySize, 98304);

    k_norm<<<512, 256>>>(ei, ej);
    k_main<<<dim3(2, 64), 256, 98304>>>();
    k_reduce<<<32, 256>>>((float*)d_out);
}

// round 6
// speedup vs baseline: 1.7391x; 1.7391x over previous
#include <cuda_runtime.h>
#include <cuda_bf16.h>
#include <stdint.h>
#include <math.h>

#define NROWS 8192
#define HALF_N 4096
#define DDIM 256

// Scratch (allocation-free rule: __device__ globals)
__device__ __nv_bfloat16 g_reps[NROWS * DDIM];  // normalized * sqrt(2*log2 e)
__device__ float g_den[NROWS];                  // denominator sums (atomic accum)
__device__ float g_pos[NROWS];                  // positive logit (natural log domain)
__device__ float g_rpart[32];
__device__ int g_sem;                           // zero-init; reset each launch

static __device__ __forceinline__ float ex2f(float x) {
    float y;
    asm("ex2.approx.f32 %0, %1;" : "=f"(y) : "f"(x));
    return y;
}

static __device__ __forceinline__ void ldsm4(uint32_t& r0, uint32_t& r1,
                                             uint32_t& r2, uint32_t& r3, uint32_t addr) {
    asm volatile("ldmatrix.sync.aligned.m8n8.x4.shared.b16 {%0,%1,%2,%3}, [%4];"
                 : "=r"(r0), "=r"(r1), "=r"(r2), "=r"(r3) : "r"(addr));
}

static __device__ __forceinline__ void mma16816(float c[4], const uint32_t a[4],
                                                const uint32_t b[2]) {
    asm volatile(
        "mma.sync.aligned.m16n8k16.row.col.f32.bf16.bf16.f32 "
        "{%0,%1,%2,%3}, {%4,%5,%6,%7}, {%8,%9}, {%0,%1,%2,%3};"
        : "+f"(c[0]), "+f"(c[1]), "+f"(c[2]), "+f"(c[3])
        : "r"(a[0]), "r"(a[1]), "r"(a[2]), "r"(a[3]), "r"(b[0]), "r"(b[1]));
}

static __device__ __forceinline__ void cpasync16(uint32_t dst, const void* src) {
    asm volatile("cp.async.cg.shared.global [%0], [%1], 16;" :: "r"(dst), "l"(src));
}
#define CP_COMMIT() asm volatile("cp.async.commit_group;")
#define CP_WAIT1()  asm volatile("cp.async.wait_group 1;")
#define CP_WAIT0()  asm volatile("cp.async.wait_group 0;")

// Fill one 128-row x 512B bf16 tile (64KB) into XOR-swizzled layout.
static __device__ __forceinline__ void fill64(uint32_t dst, const uint4* src, int tid) {
#pragma unroll
    for (int it = 0; it < 16; it++) {
        int idx = it * 256 + tid;
        int r = idx >> 5, c = idx & 31;
        cpasync16(dst + (uint32_t)(r * 32 + (c ^ (r & 7))) * 16, src + idx);
    }
}

// ---------------------------------------------------------------------------
// Kernel 1: L2-normalize rows of [emb_i; emb_j]; bf16 scaled by sqrt(2*log2 e)
// (product of two rows then carries 2*log2(e) -> base-2 logits). Also zeroes
// the global denominator accumulator.
// ---------------------------------------------------------------------------
__global__ void k_norm(const float* __restrict__ ei, const float* __restrict__ ej) {
    const float SQ = 1.69864362f;  // sqrt(2 * log2(e))
    int warp = threadIdx.x >> 5;
    int lane = threadIdx.x & 31;
    int row0 = blockIdx.x * 16 + warp * 2;

#pragma unroll
    for (int rr = 0; rr < 2; rr++) {
        int row = row0 + rr;
        const float* src = (row < HALF_N) ? (ei + (size_t)row * DDIM)
                                          : (ej + (size_t)(row - HALF_N) * DDIM);
        float4 v0 = ((const float4*)src)[lane * 2];
        float4 v1 = ((const float4*)src)[lane * 2 + 1];
        float ss = v0.x * v0.x + v0.y * v0.y + v0.z * v0.z + v0.w * v0.w
                 + v1.x * v1.x + v1.y * v1.y + v1.z * v1.z + v1.w * v1.w;
#pragma unroll
        for (int o = 16; o > 0; o >>= 1) ss += __shfl_xor_sync(0xFFFFFFFFu, ss, o);
        float sa = SQ / fmaxf(sqrtf(ss), 1e-12f);

        __nv_bfloat162* pa = (__nv_bfloat162*)(g_reps + (size_t)row * DDIM) + lane * 4;
        pa[0] = __floats2bfloat162_rn(v0.x * sa, v0.y * sa);
        pa[1] = __floats2bfloat162_rn(v0.z * sa, v0.w * sa);
        pa[2] = __floats2bfloat162_rn(v1.x * sa, v1.y * sa);
        pa[3] = __floats2bfloat162_rn(v1.z * sa, v1.w * sa);
        if (lane == 0) g_den[row] = 0.f;
    }
}

// ---------------------------------------------------------------------------
// Kernel 2: symmetric fused GEMM + exp + row/col sums over the UPPER TRIANGLE
// of the 64x64 grid of 128x128 blocks (2080 blocks). 128 CTAs; CTA (p,j):
// stripe pair rb=p (64-p tiles) + rb=63-p (p+1 tiles) = 65 tiles, split j of 4.
// Each block contributes row-sums (rb rows) and, if off-diagonal, col-sums
// (cb rows) via float atomicAdd into g_den. Positive pairs = local diagonal
// of blocks with cb == rb+32. Self-diagonal masked in blocks rb == cb.
// smem: A 64KB resident + B double buffer 2x64KB.
// ---------------------------------------------------------------------------
__global__ void __launch_bounds__(256) k_main() {
    extern __shared__ unsigned char smem[];
    const float LN2 = 0.6931471805599453f;

    int tid = threadIdx.x;
    int lane = tid & 31;
    int warp = tid >> 5;
    int wm = warp >> 1;   // 0..3: 32-row group
    int wn = warp & 1;    // 0..1: 64-col half
    int p = blockIdx.x >> 2;
    int j = blockIdx.x & 3;
    int n1 = 64 - p;      // tiles in stripe rb=p

    uint32_t sb = (uint32_t)__cvta_generic_to_shared(smem);
    uint32_t Abase = sb;
    uint32_t Bbuf[2] = {sb + 65536u, sb + 131072u};

    const uint4* reps4 = (const uint4*)g_reps;

    // decode tile index -> (rb, cb)
#define DEC(ix, rb_, cb_) do { \
        if ((ix) < n1) { rb_ = p; cb_ = p + (ix); } \
        else { rb_ = 63 - p; cb_ = 63 - p + ((ix) - n1); } } while (0)

    int idx = j;
    int rb, cb;
    DEC(idx, rb, cb);

    // Prologue: A(rb) + B0(cb) in group 1; B1(next cb) in group 2.
    fill64(Abase, reps4 + (size_t)(rb * 128) * 32, tid);
    fill64(Bbuf[0], reps4 + (size_t)(cb * 128) * 32, tid);
    CP_COMMIT();
    int idx_n = idx + 4;
    int rb_n = 0, cb_n = 0;
    if (idx_n < 65) {
        DEC(idx_n, rb_n, cb_n);
        fill64(Bbuf[1], reps4 + (size_t)(cb_n * 128) * 32, tid);
        CP_COMMIT();
        CP_WAIT1();
    } else {
        CP_COMMIT();  // empty group keeps accounting uniform
        CP_WAIT1();
    }
    __syncthreads();

    int cur_rb = rb;
    int b = 0;
    float s[4] = {0.f, 0.f, 0.f, 0.f};

    int aRow0 = wm * 32 + (lane & 15);
    int aCo = lane >> 4;
    int bRowBase = wn * 64 + (lane & 7) + ((lane & 16) >> 1);
    int bCo = (lane >> 3) & 1;

#pragma unroll 1
    while (true) {
        uint32_t Bs = Bbuf[b];

        float acc[2][8][4];
#pragma unroll
        for (int mt = 0; mt < 2; mt++)
#pragma unroll
            for (int nt = 0; nt < 8; nt++)
#pragma unroll
                for (int e = 0; e < 4; e++) acc[mt][nt][e] = 0.f;

#pragma unroll
        for (int ks = 0; ks < 16; ks++) {
            uint32_t a[2][4];
#pragma unroll
            for (int mt = 0; mt < 2; mt++) {
                int r = aRow0 + mt * 16;
                uint32_t addr = Abase + r * 512 + ((((ks * 2) + aCo) ^ (r & 7)) << 4);
                ldsm4(a[mt][0], a[mt][1], a[mt][2], a[mt][3], addr);
            }
            uint32_t bf[8][2];
#pragma unroll
            for (int nb = 0; nb < 4; nb++) {
                int r = bRowBase + nb * 16;
                uint32_t addr = Bs + r * 512 + ((((ks * 2) + bCo) ^ (r & 7)) << 4);
                uint32_t r0, r1, r2, r3;
                ldsm4(r0, r1, r2, r3, addr);
                bf[nb * 2][0] = r0;     bf[nb * 2][1] = r1;
                bf[nb * 2 + 1][0] = r2; bf[nb * 2 + 1][1] = r3;
            }
#pragma unroll
            for (int mt = 0; mt < 2; mt++)
#pragma unroll
                for (int nt = 0; nt < 8; nt++) mma16816(acc[mt][nt], a[mt], bf[nt]);
        }

        // ---- Epilogue: exps, row sums (registers), col sums (shfl+atomics).
        bool diagblk = (rb == cb);
        bool posblk = (cb == rb + 32);
        bool special = diagblk || posblk;
        float cs[16];
#pragma unroll
        for (int k = 0; k < 16; k++) cs[k] = 0.f;

#pragma unroll
        for (int mt = 0; mt < 2; mt++) {
            int lrA = wm * 32 + mt * 16 + (lane >> 2);
            int lrB = lrA + 8;
#pragma unroll
            for (int nt = 0; nt < 8; nt++) {
                float vx = acc[mt][nt][0], vy = acc[mt][nt][1];
                float vz = acc[mt][nt][2], vw = acc[mt][nt][3];
                int lc = wn * 64 + nt * 8 + (lane & 3) * 2;
                float e0 = ex2f(vx), e1 = ex2f(vy), e2 = ex2f(vz), e3 = ex2f(vw);
                if (special) {
                    if (lc == lrA) {
                        if (diagblk) e0 = 0.f;
                        else { int gr = rb * 128 + lrA; float pv = vx * LN2;
                               g_pos[gr] = pv; g_pos[gr + 4096] = pv; }
                    }
                    if (lc + 1 == lrA) {
                        if (diagblk) e1 = 0.f;
                        else { int gr = rb * 128 + lrA; float pv = vy * LN2;
                               g_pos[gr] = pv; g_pos[gr + 4096] = pv; }
                    }
                    if (lc == lrB) {
                        if (diagblk) e2 = 0.f;
                        else { int gr = rb * 128 + lrB; float pv = vz * LN2;
                               g_pos[gr] = pv; g_pos[gr + 4096] = pv; }
                    }
                    if (lc + 1 == lrB) {
                        if (diagblk) e3 = 0.f;
                        else { int gr = rb * 128 + lrB; float pv = vw * LN2;
                               g_pos[gr] = pv; g_pos[gr + 4096] = pv; }
                    }
                }
                s[mt * 2 + 0] += e0 + e1;
                s[mt * 2 + 1] += e2 + e3;
                cs[nt * 2 + 0] += e0 + e2;
                cs[nt * 2 + 1] += e1 + e3;
            }
        }

        if (!diagblk) {
#pragma unroll
            for (int k = 0; k < 16; k++) {
                cs[k] += __shfl_xor_sync(0xFFFFFFFFu, cs[k], 4);
                cs[k] += __shfl_xor_sync(0xFFFFFFFFu, cs[k], 8);
                cs[k] += __shfl_xor_sync(0xFFFFFFFFu, cs[k], 16);
            }
            if (lane < 4) {
                int cbase = cb * 128 + wn * 64 + lane * 2;
#pragma unroll
                for (int nt = 0; nt < 8; nt++) {
                    atomicAdd(&g_den[cbase + nt * 8 + 0], cs[nt * 2 + 0]);
                    atomicAdd(&g_den[cbase + nt * 8 + 1], cs[nt * 2 + 1]);
                }
            }
        }

        __syncthreads();  // all warps done reading B[b] (and As before reload)

        // Prefetch tile idx+8 into the just-freed buffer.
        int idx_p = idx + 8;
        if (idx_p < 65) {
            int rbp, cbp;
            DEC(idx_p, rbp, cbp);
            fill64(Bbuf[b], reps4 + (size_t)(cbp * 128) * 32, tid);
        }
        CP_COMMIT();  // possibly empty; keeps WAIT1 semantics uniform

        if (idx_n >= 65) break;
        idx = idx_n; rb = rb_n; cb = cb_n;
        idx_n += 4;
        if (idx_n < 65) DEC(idx_n, rb_n, cb_n);
        b ^= 1;

        if (rb != cur_rb) {
            // Flush row sums for the old stripe, load new A, drain everything.
#pragma unroll
            for (int i2 = 0; i2 < 4; i2++) {
                s[i2] += __shfl_xor_sync(0xFFFFFFFFu, s[i2], 1);
                s[i2] += __shfl_xor_sync(0xFFFFFFFFu, s[i2], 2);
            }
            if ((lane & 3) == 0) {
                int r = cur_rb * 128 + wm * 32 + (lane >> 2);
                atomicAdd(&g_den[r], s[0]);
                atomicAdd(&g_den[r + 8], s[1]);
                atomicAdd(&g_den[r + 16], s[2]);
                atomicAdd(&g_den[r + 24], s[3]);
            }
            s[0] = s[1] = s[2] = s[3] = 0.f;
            cur_rb = rb;
            fill64(Abase, reps4 + (size_t)(rb * 128) * 32, tid);
            CP_COMMIT();
            CP_WAIT0();
            __syncthreads();
        } else {
            CP_WAIT1();      // next tile's B buffer complete (this thread)
            __syncthreads(); // ... and everyone else's
        }
    }

    // Final row-sum flush for the last stripe.
#pragma unroll
    for (int i2 = 0; i2 < 4; i2++) {
        s[i2] += __shfl_xor_sync(0xFFFFFFFFu, s[i2], 1);
        s[i2] += __shfl_xor_sync(0xFFFFFFFFu, s[i2], 2);
    }
    if ((lane & 3) == 0) {
        int r = cur_rb * 128 + wm * 32 + (lane >> 2);
        atomicAdd(&g_den[r], s[0]);
        atomicAdd(&g_den[r + 8], s[1]);
        atomicAdd(&g_den[r + 16], s[2]);
        atomicAdd(&g_den[r + 24], s[3]);
    }
#undef DEC
}

// ---------------------------------------------------------------------------
// Kernel 3: final reduction -> scalar loss (deterministic fixed-order finish).
// ---------------------------------------------------------------------------
__global__ void k_reduce(float* __restrict__ out) {
    __shared__ float red[256];
    __shared__ int isLast;
    int tid = threadIdx.x;
    int r = blockIdx.x * 256 + tid;
    red[tid] = logf(g_den[r]) - g_pos[r];
    __syncthreads();
#pragma unroll
    for (int o = 128; o > 0; o >>= 1) {
        if (tid < o) red[tid] += red[tid + o];
        __syncthreads();
    }
    if (tid == 0) {
        g_rpart[blockIdx.x] = red[0];
        __threadfence();
        int old = atomicAdd(&g_sem, 1);
        isLast = (old == 31);
    }
    __syncthreads();
    if (tid == 0 && isLast) {
        __threadfence();
        volatile float* rp = g_rpart;
        float a = 0.f;
        for (int i = 0; i < 32; i++) a += rp[i];
        out[0] = a * (1.0f / 8192.0f);
        g_sem = 0;
    }
}

extern "C" void kernel_launch(void* const* d_in, const int* in_sizes, int n_in,
                              void* d_out, int out_size) {
    const float* ei = (const float*)d_in[0];
    const float* ej = (const float*)d_in[1];
    (void)in_sizes; (void)n_in; (void)out_size;

    cudaFuncSetAttribute(k_main, cudaFuncAttributeMaxDynamicSharedMemorySize, 196608);

    k_norm<<<512, 256>>>(ei, ej);
    k_main<<<128, 256, 196608>>>();
    k_reduce<<<32, 256>>>((float*)d_out);
}

// round 7
// speedup vs baseline: 1.7451x; 1.0034x over previous
#include <cuda_runtime.h>
#include <cuda_bf16.h>
#include <stdint.h>
#include <math.h>

#define NROWS 8192
#define HALF_N 4096
#define DDIM 256

// Scratch (allocation-free rule: __device__ globals)
__device__ __nv_bfloat16 g_reps[NROWS * DDIM];  // normalized * sqrt(2*log2 e)
__device__ float g_den[NROWS];                  // denominator sums (atomic accum)
__device__ float g_pos[NROWS];                  // positive logit (natural log domain)
__device__ float g_rpart[32];
__device__ int g_sem;                           // zero-init; reset each launch

static __device__ __forceinline__ float ex2f(float x) {
    float y;
    asm("ex2.approx.f32 %0, %1;" : "=f"(y) : "f"(x));
    return y;
}

static __device__ __forceinline__ void ldsm4(uint32_t& r0, uint32_t& r1,
                                             uint32_t& r2, uint32_t& r3, uint32_t addr) {
    asm volatile("ldmatrix.sync.aligned.m8n8.x4.shared.b16 {%0,%1,%2,%3}, [%4];"
                 : "=r"(r0), "=r"(r1), "=r"(r2), "=r"(r3) : "r"(addr));
}

static __device__ __forceinline__ void mma16816(float c[4], const uint32_t a[4],
                                                const uint32_t b[2]) {
    asm volatile(
        "mma.sync.aligned.m16n8k16.row.col.f32.bf16.bf16.f32 "
        "{%0,%1,%2,%3}, {%4,%5,%6,%7}, {%8,%9}, {%0,%1,%2,%3};"
        : "+f"(c[0]), "+f"(c[1]), "+f"(c[2]), "+f"(c[3])
        : "r"(a[0]), "r"(a[1]), "r"(a[2]), "r"(a[3]), "r"(b[0]), "r"(b[1]));
}

static __device__ __forceinline__ void cpasync16(uint32_t dst, const void* src) {
    asm volatile("cp.async.cg.shared.global [%0], [%1], 16;" :: "r"(dst), "l"(src));
}
#define CP_COMMIT() asm volatile("cp.async.commit_group;")
#define CP_WAIT1()  asm volatile("cp.async.wait_group 1;")
#define CP_WAIT0()  asm volatile("cp.async.wait_group 0;")

// Fill one 128-row x 512B bf16 tile (64KB) into XOR-swizzled layout.
static __device__ __forceinline__ void fill64(uint32_t dst, const uint4* src, int tid) {
#pragma unroll
    for (int it = 0; it < 16; it++) {
        int idx = it * 256 + tid;
        int r = idx >> 5, c = idx & 31;
        cpasync16(dst + (uint32_t)(r * 32 + (c ^ (r & 7))) * 16, src + idx);
    }
}

// ---------------------------------------------------------------------------
// Kernel 1: L2-normalize rows of [emb_i; emb_j]; bf16 scaled by sqrt(2*log2 e).
// Also zeroes the global denominator accumulator.
// ---------------------------------------------------------------------------
__global__ void k_norm(const float* __restrict__ ei, const float* __restrict__ ej) {
    const float SQ = 1.69864362f;  // sqrt(2 * log2(e))
    int warp = threadIdx.x >> 5;
    int lane = threadIdx.x & 31;
    int row0 = blockIdx.x * 16 + warp * 2;

#pragma unroll
    for (int rr = 0; rr < 2; rr++) {
        int row = row0 + rr;
        const float* src = (row < HALF_N) ? (ei + (size_t)row * DDIM)
                                          : (ej + (size_t)(row - HALF_N) * DDIM);
        float4 v0 = ((const float4*)src)[lane * 2];
        float4 v1 = ((const float4*)src)[lane * 2 + 1];
        float ss = v0.x * v0.x + v0.y * v0.y + v0.z * v0.z + v0.w * v0.w
                 + v1.x * v1.x + v1.y * v1.y + v1.z * v1.z + v1.w * v1.w;
#pragma unroll
        for (int o = 16; o > 0; o >>= 1) ss += __shfl_xor_sync(0xFFFFFFFFu, ss, o);
        float sa = SQ / fmaxf(sqrtf(ss), 1e-12f);

        __nv_bfloat162* pa = (__nv_bfloat162*)(g_reps + (size_t)row * DDIM) + lane * 4;
        pa[0] = __floats2bfloat162_rn(v0.x * sa, v0.y * sa);
        pa[1] = __floats2bfloat162_rn(v0.z * sa, v0.w * sa);
        pa[2] = __floats2bfloat162_rn(v1.x * sa, v1.y * sa);
        pa[3] = __floats2bfloat162_rn(v1.z * sa, v1.w * sa);
        if (lane == 0) g_den[row] = 0.f;
    }
}

// ---------------------------------------------------------------------------
// Kernel 2: symmetric fused GEMM + exp + row/col sums over the upper triangle,
// with the EPILOGUE OF TILE t SOFTWARE-PIPELINED UNDER THE MMA LOOP OF TILE
// t+1 (ping-pong accumulators, compile-time parity). Per-tile column-sum
// shuffle reductions + atomics are spread across ks=8..15 chunks.
// 128 CTAs = 32 stripe-pairs x 4; B double-buffered cp.async; A resident.
// ---------------------------------------------------------------------------
__global__ void __launch_bounds__(256, 1) k_main() {
    extern __shared__ unsigned char smem[];
    const float LN2 = 0.6931471805599453f;

    int tid = threadIdx.x;
    int lane = tid & 31;
    int warp = tid >> 5;
    int wm = warp >> 1;   // 0..3: 32-row group
    int wn = warp & 1;    // 0..1: 64-col half
    int p = blockIdx.x >> 2;
    int j = blockIdx.x & 3;

    uint32_t sb = (uint32_t)__cvta_generic_to_shared(smem);
    uint32_t Abase = sb;
    uint32_t Bbuf0 = sb + 65536u, Bbuf1 = sb + 131072u;

    const uint4* reps4 = (const uint4*)g_reps;

    int aRow0 = wm * 32 + (lane & 15);
    int aCo = lane >> 4;
    int bRowBase = wn * 64 + (lane & 7) + ((lane & 16) >> 1);
    int bCo = (lane >> 3) & 1;

    float s[4] = {0.f, 0.f, 0.f, 0.f};
    float acc0[2][8][4], acc1[2][8][4];
    float cs[16];

    auto fillB = [&](uint32_t dst, int cbb) {
        fill64(dst, reps4 + (size_t)(cbb * 128) * 32, tid);
    };

    // One fused step: MMA tile into aN from Bs; epilogue of aO (block col ocb).
    auto step = [&](float (&aN)[2][8][4], float (&aO)[2][8][4], uint32_t Bs,
                    bool doEpi, int rbb, int ocb) {
        bool diagb = doEpi && (rbb == ocb);
        bool posb = doEpi && (ocb == rbb + 32);
        bool special = diagb || posb;
#pragma unroll
        for (int k = 0; k < 16; k++) cs[k] = 0.f;
#pragma unroll
        for (int mt = 0; mt < 2; mt++)
#pragma unroll
            for (int nt = 0; nt < 8; nt++)
#pragma unroll
                for (int e = 0; e < 4; e++) aN[mt][nt][e] = 0.f;

#pragma unroll
        for (int ks = 0; ks < 16; ks++) {
            uint32_t a[2][4];
#pragma unroll
            for (int mt = 0; mt < 2; mt++) {
                int r = aRow0 + mt * 16;
                uint32_t addr = Abase + r * 512 + ((((ks * 2) + aCo) ^ (r & 7)) << 4);
                ldsm4(a[mt][0], a[mt][1], a[mt][2], a[mt][3], addr);
            }
            uint32_t bf[8][2];
#pragma unroll
            for (int nb = 0; nb < 4; nb++) {
                int r = bRowBase + nb * 16;
                uint32_t addr = Bs + r * 512 + ((((ks * 2) + bCo) ^ (r & 7)) << 4);
                uint32_t r0, r1, r2, r3;
                ldsm4(r0, r1, r2, r3, addr);
                bf[nb * 2][0] = r0;     bf[nb * 2][1] = r1;
                bf[nb * 2 + 1][0] = r2; bf[nb * 2 + 1][1] = r3;
            }
#pragma unroll
            for (int mt = 0; mt < 2; mt++)
#pragma unroll
                for (int nt = 0; nt < 8; nt++) mma16816(aN[mt][nt], a[mt], bf[nt]);

            // ---- interleaved epilogue chunk of old tile: (mt_, nt_) = ks.
            if (doEpi) {
                const int mt_ = ks >> 3, nt_ = ks & 7;
                int lrA = wm * 32 + mt_ * 16 + (lane >> 2);
                int lrB = lrA + 8;
                float vx = aO[mt_][nt_][0], vy = aO[mt_][nt_][1];
                float vz = aO[mt_][nt_][2], vw = aO[mt_][nt_][3];
                int lc = wn * 64 + nt_ * 8 + (lane & 3) * 2;
                float e0 = ex2f(vx), e1 = ex2f(vy), e2 = ex2f(vz), e3 = ex2f(vw);
                if (special) {
                    // rb==cb: local diag mask. cb==rb+32: local diag = positive.
                    if (lc == lrA) {
                        if (diagb) e0 = 0.f;
                        else { int gr = rbb * 128 + lrA; float pv = vx * LN2;
                               g_pos[gr] = pv; g_pos[gr + 4096] = pv; }
                    }
                    if (lc + 1 == lrA) {
                        if (diagb) e1 = 0.f;
                        else { int gr = rbb * 128 + lrA; float pv = vy * LN2;
                               g_pos[gr] = pv; g_pos[gr + 4096] = pv; }
                    }
                    if (lc == lrB) {
                        if (diagb) e2 = 0.f;
                        else { int gr = rbb * 128 + lrB; float pv = vz * LN2;
                               g_pos[gr] = pv; g_pos[gr + 4096] = pv; }
                    }
                    if (lc + 1 == lrB) {
                        if (diagb) e3 = 0.f;
                        else { int gr = rbb * 128 + lrB; float pv = vw * LN2;
                               g_pos[gr] = pv; g_pos[gr + 4096] = pv; }
                    }
                }
                s[mt_ * 2 + 0] += e0 + e1;
                s[mt_ * 2 + 1] += e2 + e3;
                cs[nt_ * 2 + 0] += e0 + e2;
                cs[nt_ * 2 + 1] += e1 + e3;
                // Column-sum finalize for nt_ once both mt passes done (ks>=8).
                if (ks >= 8 && !diagb) {
                    float c0 = cs[nt_ * 2 + 0], c1 = cs[nt_ * 2 + 1];
                    c0 += __shfl_xor_sync(0xFFFFFFFFu, c0, 4);
                    c1 += __shfl_xor_sync(0xFFFFFFFFu, c1, 4);
                    c0 += __shfl_xor_sync(0xFFFFFFFFu, c0, 8);
                    c1 += __shfl_xor_sync(0xFFFFFFFFu, c1, 8);
                    c0 += __shfl_xor_sync(0xFFFFFFFFu, c0, 16);
                    c1 += __shfl_xor_sync(0xFFFFFFFFu, c1, 16);
                    if (lane < 4) {
                        int cbase = ocb * 128 + wn * 64 + nt_ * 8 + lane * 2;
                        atomicAdd(&g_den[cbase + 0], c0);
                        atomicAdd(&g_den[cbase + 1], c1);
                    }
                }
            }
        }
    };

    // Standalone epilogue (drain of a segment's last tile).
    auto epi_full = [&](float (&aO)[2][8][4], int rbb, int ocb) {
        bool diagb = (rbb == ocb);
        bool posb = (ocb == rbb + 32);
        bool special = diagb || posb;
#pragma unroll
        for (int k = 0; k < 16; k++) cs[k] = 0.f;
#pragma unroll
        for (int ks = 0; ks < 16; ks++) {
            const int mt_ = ks >> 3, nt_ = ks & 7;
            int lrA = wm * 32 + mt_ * 16 + (lane >> 2);
            int lrB = lrA + 8;
            float vx = aO[mt_][nt_][0], vy = aO[mt_][nt_][1];
            float vz = aO[mt_][nt_][2], vw = aO[mt_][nt_][3];
            int lc = wn * 64 + nt_ * 8 + (lane & 3) * 2;
            float e0 = ex2f(vx), e1 = ex2f(vy), e2 = ex2f(vz), e3 = ex2f(vw);
            if (special) {
                if (lc == lrA) {
                    if (diagb) e0 = 0.f;
                    else { int gr = rbb * 128 + lrA; float pv = vx * LN2;
                           g_pos[gr] = pv; g_pos[gr + 4096] = pv; }
                }
                if (lc + 1 == lrA) {
                    if (diagb) e1 = 0.f;
                    else { int gr = rbb * 128 + lrA; float pv = vy * LN2;
                           g_pos[gr] = pv; g_pos[gr + 4096] = pv; }
                }
                if (lc == lrB) {
                    if (diagb) e2 = 0.f;
                    else { int gr = rbb * 128 + lrB; float pv = vz * LN2;
                           g_pos[gr] = pv; g_pos[gr + 4096] = pv; }
                }
                if (lc + 1 == lrB) {
                    if (diagb) e3 = 0.f;
                    else { int gr = rbb * 128 + lrB; float pv = vw * LN2;
                           g_pos[gr] = pv; g_pos[gr + 4096] = pv; }
                }
            }
            s[mt_ * 2 + 0] += e0 + e1;
            s[mt_ * 2 + 1] += e2 + e3;
            cs[nt_ * 2 + 0] += e0 + e2;
            cs[nt_ * 2 + 1] += e1 + e3;
            if (ks >= 8 && !diagb) {
                float c0 = cs[nt_ * 2 + 0], c1 = cs[nt_ * 2 + 1];
                c0 += __shfl_xor_sync(0xFFFFFFFFu, c0, 4);
                c1 += __shfl_xor_sync(0xFFFFFFFFu, c1, 4);
                c0 += __shfl_xor_sync(0xFFFFFFFFu, c0, 8);
                c1 += __shfl_xor_sync(0xFFFFFFFFu, c1, 8);
                c0 += __shfl_xor_sync(0xFFFFFFFFu, c0, 16);
                c1 += __shfl_xor_sync(0xFFFFFFFFu, c1, 16);
                if (lane < 4) {
                    int cbase = ocb * 128 + wn * 64 + nt_ * 8 + lane * 2;
                    atomicAdd(&g_den[cbase + 0], c0);
                    atomicAdd(&g_den[cbase + 1], c1);
                }
            }
        }
    };

    auto flush_rows = [&](int rbb) {
#pragma unroll
        for (int i2 = 0; i2 < 4; i2++) {
            s[i2] += __shfl_xor_sync(0xFFFFFFFFu, s[i2], 1);
            s[i2] += __shfl_xor_sync(0xFFFFFFFFu, s[i2], 2);
        }
        if ((lane & 3) == 0) {
            int r = rbb * 128 + wm * 32 + (lane >> 2);
            atomicAdd(&g_den[r], s[0]);
            atomicAdd(&g_den[r + 8], s[1]);
            atomicAdd(&g_den[r + 16], s[2]);
            atomicAdd(&g_den[r + 24], s[3]);
        }
        s[0] = s[1] = s[2] = s[3] = 0.f;
    };

    // Run one row-stripe segment: tiles (rbb, cb0 + 4*t), t = 0..nt-1.
    auto run_seg = [&](int rbb, int cb0, int ntl) {
        if (ntl <= 0) return;
        __syncthreads();  // A buffer free (no readers in flight)
        fill64(Abase, reps4 + (size_t)(rbb * 128) * 32, tid);
        fillB(Bbuf0, cb0);
        CP_COMMIT();
        if (ntl > 1) {
            fillB(Bbuf1, cb0 + 4);
            CP_COMMIT();
            CP_WAIT1();
        } else {
            CP_WAIT0();
        }
        __syncthreads();

        step(acc0, acc1, Bbuf0, false, rbb, 0);  // tile 0 -> acc0

#pragma unroll 1
        for (int base = 1; base < ntl; base += 2) {
            // tile t=base (odd) -> acc1; epilogue tile base-1 in acc0.
            {
                int t = base;
                __syncthreads();
                if (t + 1 < ntl) fillB(Bbuf0, cb0 + 4 * (t + 1));
                CP_COMMIT();
                if (t == ntl - 1) { CP_WAIT0(); } else { CP_WAIT1(); }
                __syncthreads();
                step(acc1, acc0, Bbuf1, true, rbb, cb0 + 4 * (t - 1));
            }
            if (base + 1 < ntl) {
                int t = base + 1;   // even -> acc0; epilogue acc1.
                __syncthreads();
                if (t + 1 < ntl) fillB(Bbuf1, cb0 + 4 * (t + 1));
                CP_COMMIT();
                if (t == ntl - 1) { CP_WAIT0(); } else { CP_WAIT1(); }
                __syncthreads();
                step(acc0, acc1, Bbuf0, true, rbb, cb0 + 4 * (t - 1));
            }
        }
        // Drain last tile's epilogue (parity: even tile -> acc0).
        if (ntl & 1) epi_full(acc0, rbb, cb0 + 4 * (ntl - 1));
        else epi_full(acc1, rbb, cb0 + 4 * (ntl - 1));
        flush_rows(rbb);
    };

    // Stripe-pair schedule: pair p = stripes rb=p (64-p tiles) and rb=63-p
    // (p+1 tiles), 65 tiles total, strided 4 ways by j.
    int n1 = 64 - p;
    int c1 = (n1 - 1 - j) / 4 + 1;
    int g0 = n1 + ((j - n1) & 3);
    int c2 = (g0 <= 64) ? (64 - g0) / 4 + 1 : 0;

    run_seg(p, p + j, c1);
    run_seg(63 - p, 63 - p + (g0 - n1), c2);
}

// ---------------------------------------------------------------------------
// Kernel 3: final reduction -> scalar loss (deterministic fixed-order finish).
// ---------------------------------------------------------------------------
__global__ void k_reduce(float* __restrict__ out) {
    __shared__ float red[256];
    __shared__ int isLast;
    int tid = threadIdx.x;
    int r = blockIdx.x * 256 + tid;
    red[tid] = logf(g_den[r]) - g_pos[r];
    __syncthreads();
#pragma unroll
    for (int o = 128; o > 0; o >>= 1) {
        if (tid < o) red[tid] += red[tid + o];
        __syncthreads();
    }
    if (tid == 0) {
        g_rpart[blockIdx.x] = red[0];
        __threadfence();
        int old = atomicAdd(&g_sem, 1);
        isLast = (old == 31);
    }
    __syncthreads();
    if (tid == 0 && isLast) {
        __threadfence();
        volatile float* rp = g_rpart;
        float a = 0.f;
        for (int i = 0; i < 32; i++) a += rp[i];
        out[0] = a * (1.0f / 8192.0f);
        g_sem = 0;
    }
}

extern "C" void kernel_launch(void* const* d_in, const int* in_sizes, int n_in,
                              void* d_out, int out_size) {
    const float* ei = (const float*)d_in[0];
    const float* ej = (const float*)d_in[1];
    (void)in_sizes; (void)n_in; (void)out_size;

    cudaFuncSetAttribute(k_main, cudaFuncAttributeMaxDynamicSharedMemorySize, 196608);

    k_norm<<<512, 256>>>(ei, ej);
    k_main<<<128, 256, 196608>>>();
    k_reduce<<<32, 256>>>((float*)d_out);
}

// round 8
// speedup vs baseline: 2.0185x; 1.1566x over previous
#include <cuda_runtime.h>
#include <cuda_bf16.h>
#include <stdint.h>
#include <math.h>

#define NROWS 8192
#define HALF_N 4096
#define DDIM 256
#define NCTA 148

// Scratch (allocation-free rule: __device__ globals)
__device__ __nv_bfloat16 g_reps[NROWS * DDIM];  // normalized * sqrt(2*log2 e)
__device__ float g_den[NROWS];                  // denominator sums (atomic accum)
__device__ float g_pos[NROWS];                  // positive logit (natural log domain)
__device__ float g_rpart[32];
__device__ int g_sem;                           // zero-init; reset each launch

static __device__ __forceinline__ float ex2f(float x) {
    float y;
    asm("ex2.approx.f32 %0, %1;" : "=f"(y) : "f"(x));
    return y;
}

static __device__ __forceinline__ void ldsm4(uint32_t& r0, uint32_t& r1,
                                             uint32_t& r2, uint32_t& r3, uint32_t addr) {
    asm volatile("ldmatrix.sync.aligned.m8n8.x4.shared.b16 {%0,%1,%2,%3}, [%4];"
                 : "=r"(r0), "=r"(r1), "=r"(r2), "=r"(r3) : "r"(addr));
}

static __device__ __forceinline__ void mma16816(float c[4], const uint32_t a[4],
                                                const uint32_t b[2]) {
    asm volatile(
        "mma.sync.aligned.m16n8k16.row.col.f32.bf16.bf16.f32 "
        "{%0,%1,%2,%3}, {%4,%5,%6,%7}, {%8,%9}, {%0,%1,%2,%3};"
        : "+f"(c[0]), "+f"(c[1]), "+f"(c[2]), "+f"(c[3])
        : "r"(a[0]), "r"(a[1]), "r"(a[2]), "r"(a[3]), "r"(b[0]), "r"(b[1]));
}

static __device__ __forceinline__ void cpasync16(uint32_t dst, const void* src) {
    asm volatile("cp.async.cg.shared.global [%0], [%1], 16;" :: "r"(dst), "l"(src));
}
#define CP_COMMIT() asm volatile("cp.async.commit_group;")
#define CP_WAIT1()  asm volatile("cp.async.wait_group 1;")
#define CP_WAIT0()  asm volatile("cp.async.wait_group 0;")

// Advance (rb, cb) one tile along the upper triangle (rb-major, cb contiguous).
#define ADV(r_, c_) do { if ((c_) >= 63) { if ((r_) < 63) { (r_)++; (c_) = (r_); } } \
                         else (c_)++; } while (0)

// Fill one 128-row x 512B bf16 tile (64KB) into XOR-swizzled layout.
static __device__ __forceinline__ void fill64(uint32_t dst, const uint4* src, int tid) {
#pragma unroll
    for (int it = 0; it < 16; it++) {
        int idx = it * 256 + tid;
        int r = idx >> 5, c = idx & 31;
        cpasync16(dst + (uint32_t)(r * 32 + (c ^ (r & 7))) * 16, src + idx);
    }
}

// ---------------------------------------------------------------------------
// Kernel 1: L2-normalize rows of [emb_i; emb_j]; bf16 scaled by sqrt(2*log2 e).
// Both rows' loads issued before either reduction (ILP). Zeroes g_den.
// ---------------------------------------------------------------------------
__global__ void k_norm(const float* __restrict__ ei, const float* __restrict__ ej) {
    const float SQ = 1.69864362f;  // sqrt(2 * log2(e))
    int warp = threadIdx.x >> 5;
    int lane = threadIdx.x & 31;
    int row = blockIdx.x * 16 + warp * 2;   // pair (row, row+1), same input half

    const float* s0 = (row < HALF_N) ? (ei + (size_t)row * DDIM)
                                     : (ej + (size_t)(row - HALF_N) * DDIM);
    const float* s1 = s0 + DDIM;
    float4 a0 = ((const float4*)s0)[lane * 2];
    float4 a1 = ((const float4*)s0)[lane * 2 + 1];
    float4 b0 = ((const float4*)s1)[lane * 2];
    float4 b1 = ((const float4*)s1)[lane * 2 + 1];

    float sa = a0.x * a0.x + a0.y * a0.y + a0.z * a0.z + a0.w * a0.w
             + a1.x * a1.x + a1.y * a1.y + a1.z * a1.z + a1.w * a1.w;
    float sb = b0.x * b0.x + b0.y * b0.y + b0.z * b0.z + b0.w * b0.w
             + b1.x * b1.x + b1.y * b1.y + b1.z * b1.z + b1.w * b1.w;
#pragma unroll
    for (int o = 16; o > 0; o >>= 1) {
        sa += __shfl_xor_sync(0xFFFFFFFFu, sa, o);
        sb += __shfl_xor_sync(0xFFFFFFFFu, sb, o);
    }
    float fa = SQ / fmaxf(sqrtf(sa), 1e-12f);
    float fb = SQ / fmaxf(sqrtf(sb), 1e-12f);

    __nv_bfloat162* pa = (__nv_bfloat162*)(g_reps + (size_t)row * DDIM) + lane * 4;
    __nv_bfloat162* pb = (__nv_bfloat162*)(g_reps + (size_t)(row + 1) * DDIM) + lane * 4;
    pa[0] = __floats2bfloat162_rn(a0.x * fa, a0.y * fa);
    pa[1] = __floats2bfloat162_rn(a0.z * fa, a0.w * fa);
    pa[2] = __floats2bfloat162_rn(a1.x * fa, a1.y * fa);
    pa[3] = __floats2bfloat162_rn(a1.z * fa, a1.w * fa);
    pb[0] = __floats2bfloat162_rn(b0.x * fb, b0.y * fb);
    pb[1] = __floats2bfloat162_rn(b0.z * fb, b0.w * fb);
    pb[2] = __floats2bfloat162_rn(b1.x * fb, b1.y * fb);
    pb[3] = __floats2bfloat162_rn(b1.z * fb, b1.w * fb);
    if (lane == 0) { g_den[row] = 0.f; g_den[row + 1] = 0.f; }
}

// ---------------------------------------------------------------------------
// Kernel 2: symmetric fused GEMM + exp + row/col sums over the upper triangle.
// 148 CTAs; 2080 tiles linearized rb-major/cb-contiguous, 14-15 tiles per CTA
// (balanced, 1 wave on the full chip). A reloaded only on stripe change; B
// double-buffered cp.async. Off-diag tiles also scatter column sums (symmetry).
// ---------------------------------------------------------------------------
__global__ void __launch_bounds__(256, 1) k_main() {
    extern __shared__ unsigned char smem[];
    const float LN2 = 0.6931471805599453f;

    int tid = threadIdx.x;
    int lane = tid & 31;
    int warp = tid >> 5;
    int wm = warp >> 1;   // 0..3: 32-row group
    int wn = warp & 1;    // 0..1: 64-col half

    uint32_t sb = (uint32_t)__cvta_generic_to_shared(smem);
    uint32_t Abase = sb;
    uint32_t Bbuf[2] = {sb + 65536u, sb + 131072u};

    const uint4* reps4 = (const uint4*)g_reps;

    // ---- balanced contiguous schedule: 2080 = 148*14 + 8
    int bId = blockIdx.x;
    int cnt = 14 + (bId < 8 ? 1 : 0);
    int i0 = bId * 14 + (bId < 8 ? bId : 8);

    int rb = 0, rem = i0;
    while (rem >= 64 - rb) { rem -= 64 - rb; rb++; }
    int cb = rb + rem;

    int rb1 = rb, cb1 = cb; ADV(rb1, cb1);   // tile i0+1
    int rbp = rb1, cbp = cb1; ADV(rbp, cbp); // prefetch ptr (i0+2)

    // Prologue.
    fill64(Abase, reps4 + (size_t)(rb * 128) * 32, tid);
    fill64(Bbuf[0], reps4 + (size_t)(cb * 128) * 32, tid);
    CP_COMMIT();
    if (cnt > 1) fill64(Bbuf[1], reps4 + (size_t)(cb1 * 128) * 32, tid);
    CP_COMMIT();
    CP_WAIT1();
    __syncthreads();

    int aRow0 = wm * 32 + (lane & 15);
    int aCo = lane >> 4;
    int bRowBase = wn * 64 + (lane & 7) + ((lane & 16) >> 1);
    int bCo = (lane >> 3) & 1;

    float s[4] = {0.f, 0.f, 0.f, 0.f};
    int b = 0;

#pragma unroll 1
    for (int k = 0; ; k++) {
        uint32_t Bs = Bbuf[b];

        float acc[2][8][4];
#pragma unroll
        for (int mt = 0; mt < 2; mt++)
#pragma unroll
            for (int nt = 0; nt < 8; nt++)
#pragma unroll
                for (int e = 0; e < 4; e++) acc[mt][nt][e] = 0.f;

#pragma unroll
        for (int ks = 0; ks < 16; ks++) {
            uint32_t a[2][4];
#pragma unroll
            for (int mt = 0; mt < 2; mt++) {
                int r = aRow0 + mt * 16;
                uint32_t addr = Abase + r * 512 + ((((ks * 2) + aCo) ^ (r & 7)) << 4);
                ldsm4(a[mt][0], a[mt][1], a[mt][2], a[mt][3], addr);
            }
            uint32_t bf[8][2];
#pragma unroll
            for (int nb = 0; nb < 4; nb++) {
                int r = bRowBase + nb * 16;
                uint32_t addr = Bs + r * 512 + ((((ks * 2) + bCo) ^ (r & 7)) << 4);
                uint32_t r0, r1, r2, r3;
                ldsm4(r0, r1, r2, r3, addr);
                bf[nb * 2][0] = r0;     bf[nb * 2][1] = r1;
                bf[nb * 2 + 1][0] = r2; bf[nb * 2 + 1][1] = r3;
            }
#pragma unroll
            for (int mt = 0; mt < 2; mt++)
#pragma unroll
                for (int nt = 0; nt < 8; nt++) mma16816(acc[mt][nt], a[mt], bf[nt]);
        }

        // ---- Epilogue: exps, row sums (registers), col sums (shfl+atomics).
        bool diagblk = (rb == cb);
        bool posblk = (cb == rb + 32);
        bool special = diagblk || posblk;
        float cs[16];
#pragma unroll
        for (int q = 0; q < 16; q++) cs[q] = 0.f;

#pragma unroll
        for (int mt = 0; mt < 2; mt++) {
            int lrA = wm * 32 + mt * 16 + (lane >> 2);
            int lrB = lrA + 8;
#pragma unroll
            for (int nt = 0; nt < 8; nt++) {
                float vx = acc[mt][nt][0], vy = acc[mt][nt][1];
                float vz = acc[mt][nt][2], vw = acc[mt][nt][3];
                int lc = wn * 64 + nt * 8 + (lane & 3) * 2;
                float e0 = ex2f(vx), e1 = ex2f(vy), e2 = ex2f(vz), e3 = ex2f(vw);
                if (special) {
                    if (lc == lrA) {
                        if (diagblk) e0 = 0.f;
                        else { int gr = rb * 128 + lrA; float pv = vx * LN2;
                               g_pos[gr] = pv; g_pos[gr + 4096] = pv; }
                    }
                    if (lc + 1 == lrA) {
                        if (diagblk) e1 = 0.f;
                        else { int gr = rb * 128 + lrA; float pv = vy * LN2;
                               g_pos[gr] = pv; g_pos[gr + 4096] = pv; }
                    }
                    if (lc == lrB) {
                        if (diagblk) e2 = 0.f;
                        else { int gr = rb * 128 + lrB; float pv = vz * LN2;
                               g_pos[gr] = pv; g_pos[gr + 4096] = pv; }
                    }
                    if (lc + 1 == lrB) {
                        if (diagblk) e3 = 0.f;
                        else { int gr = rb * 128 + lrB; float pv = vw * LN2;
                               g_pos[gr] = pv; g_pos[gr + 4096] = pv; }
                    }
                }
                s[mt * 2 + 0] += e0 + e1;
                s[mt * 2 + 1] += e2 + e3;
                cs[nt * 2 + 0] += e0 + e2;
                cs[nt * 2 + 1] += e1 + e3;
            }
        }

        if (!diagblk) {
#pragma unroll
            for (int q = 0; q < 16; q++) {
                cs[q] += __shfl_xor_sync(0xFFFFFFFFu, cs[q], 4);
                cs[q] += __shfl_xor_sync(0xFFFFFFFFu, cs[q], 8);
                cs[q] += __shfl_xor_sync(0xFFFFFFFFu, cs[q], 16);
            }
            if (lane < 4) {
                int cbase = cb * 128 + wn * 64 + lane * 2;
#pragma unroll
                for (int nt = 0; nt < 8; nt++) {
                    atomicAdd(&g_den[cbase + nt * 8 + 0], cs[nt * 2 + 0]);
                    atomicAdd(&g_den[cbase + nt * 8 + 1], cs[nt * 2 + 1]);
                }
            }
        }

        __syncthreads();  // all warps done reading B[b] (and A before reload)

        // Prefetch tile k+2 into the just-freed buffer.
        if (k + 2 < cnt)
            fill64(Bbuf[b], reps4 + (size_t)(cbp * 128) * 32, tid);
        CP_COMMIT();      // possibly empty; keeps WAIT1 accounting uniform

        if (k + 1 >= cnt) break;
        ADV(rbp, cbp);

        if (rb1 != rb) {
            // Stripe change: flush row sums, reload A, drain everything.
#pragma unroll
            for (int i2 = 0; i2 < 4; i2++) {
                s[i2] += __shfl_xor_sync(0xFFFFFFFFu, s[i2], 1);
                s[i2] += __shfl_xor_sync(0xFFFFFFFFu, s[i2], 2);
            }
            if ((lane & 3) == 0) {
                int r = rb * 128 + wm * 32 + (lane >> 2);
                atomicAdd(&g_den[r], s[0]);
                atomicAdd(&g_den[r + 8], s[1]);
                atomicAdd(&g_den[r + 16], s[2]);
                atomicAdd(&g_den[r + 24], s[3]);
            }
            s[0] = s[1] = s[2] = s[3] = 0.f;
            fill64(Abase, reps4 + (size_t)(rb1 * 128) * 32, tid);
            CP_COMMIT();
            CP_WAIT0();
        } else {
            CP_WAIT1();
        }
        __syncthreads();

        rb = rb1; cb = cb1;
        ADV(rb1, cb1);
        b ^= 1;
    }

    // Final row-sum flush.
#pragma unroll
    for (int i2 = 0; i2 < 4; i2++) {
        s[i2] += __shfl_xor_sync(0xFFFFFFFFu, s[i2], 1);
        s[i2] += __shfl_xor_sync(0xFFFFFFFFu, s[i2], 2);
    }
    if ((lane & 3) == 0) {
        int r = rb * 128 + wm * 32 + (lane >> 2);
        atomicAdd(&g_den[r], s[0]);
        atomicAdd(&g_den[r + 8], s[1]);
        atomicAdd(&g_den[r + 16], s[2]);
        atomicAdd(&g_den[r + 24], s[3]);
    }
}

// ---------------------------------------------------------------------------
// Kernel 3: final reduction -> scalar loss (deterministic fixed-order finish).
// ---------------------------------------------------------------------------
__global__ void k_reduce(float* __restrict__ out) {
    __shared__ float red[256];
    __shared__ int isLast;
    int tid = threadIdx.x;
    int r = blockIdx.x * 256 + tid;
    red[tid] = logf(g_den[r]) - g_pos[r];
    __syncthreads();
#pragma unroll
    for (int o = 128; o > 0; o >>= 1) {
        if (tid < o) red[tid] += red[tid + o];
        __syncthreads();
    }
    if (tid == 0) {
        g_rpart[blockIdx.x] = red[0];
        __threadfence();
        int old = atomicAdd(&g_sem, 1);
        isLast = (old == 31);
    }
    __syncthreads();
    if (tid == 0 && isLast) {
        __threadfence();
        volatile float* rp = g_rpart;
        float a = 0.f;
        for (int i = 0; i < 32; i++) a += rp[i];
        out[0] = a * (1.0f / 8192.0f);
        g_sem = 0;
    }
}

extern "C" void kernel_launch(void* const* d_in, const int* in_sizes, int n_in,
                              void* d_out, int out_size) {
    const float* ei = (const float*)d_in[0];
    const float* ej = (const float*)d_in[1];
    (void)in_sizes; (void)n_in; (void)out_size;

    cudaFuncSetAttribute(k_main, cudaFuncAttributeMaxDynamicSharedMemorySize, 196608);

    k_norm<<<512, 256>>>(ei, ej);
    k_main<<<NCTA, 256, 196608>>>();
    k_reduce<<<32, 256>>>((float*)d_out);
}